// round 1
// baseline (speedup 1.0000x reference)
#include <cuda_runtime.h>
#include <cstdint>

#define BIMG 16
#define NBOX 25200
#define ROWST 85
#define NCLS 80
#define KSEL 4096
#define MAXDET 300
#define CONF_TH 0.6f
#define IOU_TH 0.45f
#define MAXWH 7680.0f

// ---- device scratch (no allocations allowed) ----
__device__ uint64_t g_keys[BIMG * NBOX];          // composite (mapped masked-obj, ~idx) keys
__device__ float    g_boxes[BIMG * KSEL * 4];     // sorted xyxy boxes (no class offset)
__device__ float    g_scorea[BIMG * KSEL];        // sorted scores (-1 for invalid)
__device__ float    g_clsa[BIMG * KSEL];          // sorted class ids (float)
__device__ unsigned char g_clstmp[BIMG * NBOX];   // argmax class per original row

// order-preserving float<->uint32 map (ascending)
__device__ __forceinline__ uint32_t fmap(float f) {
    uint32_t u = __float_as_uint(f);
    return (u & 0x80000000u) ? ~u : (u | 0x80000000u);
}
__device__ __forceinline__ float funmap(uint32_t u) {
    u = (u & 0x80000000u) ? (u & 0x7FFFFFFFu) : ~u;
    return __uint_as_float(u);
}

// One block per image: build keys, radix-select exact top-K threshold, gather,
// compute scores (obj * max cls) + argmax class, bitonic sort by
// (score desc, masked-obj desc, idx asc), write sorted candidate arrays.
__global__ __launch_bounds__(1024) void select_sort_kernel(const float* __restrict__ x) {
    __shared__ uint64_t sk[KSEL];       // 32 KB: (mapped_score << 32) | mapped_masked_obj
    __shared__ uint16_t sn[KSEL];       // 8 KB: original row index
    __shared__ uint32_t hist[256];
    __shared__ uint64_t s_prefix;
    __shared__ int s_rem;
    __shared__ int s_cnt;

    const int img = blockIdx.x;
    const int tid = threadIdx.x;
    const int bs  = blockDim.x;
    const float* X = x + (size_t)img * NBOX * ROWST;
    uint64_t* keys = g_keys + (size_t)img * NBOX;

    // Phase A: composite keys (masked obj desc, idx asc) -- all distinct.
    for (int n = tid; n < NBOX; n += bs) {
        float obj = X[(size_t)n * ROWST + 4];
        float m = obj > CONF_TH ? obj : -1.0f;
        keys[n] = ((uint64_t)fmap(m) << 32) | (uint32_t)(~(uint32_t)n);
    }
    if (tid == 0) { s_prefix = 0ULL; s_rem = KSEL; s_cnt = 0; }
    __syncthreads();

    // Phase B: MSB-first 8-bit radix select of the K-th largest key (exact).
    for (int d = 7; d >= 0; --d) {
        for (int b = tid; b < 256; b += bs) hist[b] = 0;
        __syncthreads();
        const int shift = d * 8;
        const uint64_t hmask = (d == 7) ? 0ULL : ~(((uint64_t)1 << ((d + 1) * 8)) - 1ULL);
        const uint64_t pref = s_prefix;
        for (int n = tid; n < NBOX; n += bs) {
            uint64_t k = keys[n];
            if ((k & hmask) == pref) {
                uint32_t bin = (uint32_t)(k >> shift) & 0xFFu;
                unsigned am = __activemask();
                unsigned mm = __match_any_sync(am, bin);
                int leader = __ffs(mm) - 1;
                if ((int)(tid & 31) == leader) atomicAdd(&hist[bin], (uint32_t)__popc(mm));
            }
        }
        __syncthreads();
        if (tid == 0) {
            int rem = s_rem;
            int b = 255;
            for (; b > 0; --b) {
                int c = (int)hist[b];
                if (rem <= c) break;
                rem -= c;
            }
            s_prefix = pref | ((uint64_t)(uint32_t)b << shift);
            s_rem = rem;
        }
        __syncthreads();
    }
    const uint64_t T = s_prefix;   // exactly KSEL keys are >= T (keys distinct)

    // Phase C: gather candidate indices (order arbitrary; fixed by sort below)
    for (int n = tid; n < NBOX; n += bs) {
        if (keys[n] >= T) {
            int p = atomicAdd(&s_cnt, 1);
            sn[p] = (uint16_t)n;
        }
    }
    __syncthreads();

    // Phase D: per-candidate score (obj * max cls) + argmax class, one warp each.
    const int wid = tid >> 5, lane = tid & 31, nwarp = bs >> 5;
    for (int c = wid; c < KSEL; c += nwarp) {
        int n = sn[c];
        const float* row = X + (size_t)n * ROWST;
        float obj = row[4];
        float best = -1.0f; int bidx = NCLS;
        for (int j = lane; j < NCLS; j += 32) {
            float v = row[5 + j];
            if (v > best) { best = v; bidx = j; }
        }
        #pragma unroll
        for (int off = 16; off > 0; off >>= 1) {
            float ov = __shfl_down_sync(0xFFFFFFFFu, best, off);
            int   oi = __shfl_down_sync(0xFFFFFFFFu, bidx, off);
            if (ov > best || (ov == best && oi < bidx)) { best = ov; bidx = oi; }
        }
        if (lane == 0) {
            bool valid = obj > CONF_TH;
            float score = valid ? __fmul_rn(obj, best) : -1.0f;
            uint32_t mobj = fmap(valid ? obj : -1.0f);
            sk[c] = ((uint64_t)fmap(score) << 32) | (uint64_t)mobj;
            g_clstmp[(size_t)img * NBOX + n] = (unsigned char)bidx;
        }
    }
    __syncthreads();

    // Phase E: bitonic sort descending by (score, masked obj), tie -> idx asc.
    for (unsigned kk = 2; kk <= KSEL; kk <<= 1) {
        for (unsigned j = kk >> 1; j > 0; j >>= 1) {
            __syncthreads();
            for (unsigned i = tid; i < KSEL; i += bs) {
                unsigned ixj = i ^ j;
                if (ixj > i) {
                    uint64_t a = sk[i], b = sk[ixj];
                    uint16_t na = sn[i], nb = sn[ixj];
                    bool gt_i = (a > b) || (a == b && na < nb);
                    bool desc = ((i & kk) == 0);
                    if (gt_i != desc) { sk[i] = b; sk[ixj] = a; sn[i] = nb; sn[ixj] = na; }
                }
            }
        }
    }
    __syncthreads();

    // Phase F: emit sorted boxes (xyxy), score, cls (reference float op order)
    for (int r = tid; r < KSEL; r += bs) {
        int n = sn[r];
        float score = funmap((uint32_t)(sk[r] >> 32));
        const float* row = X + (size_t)n * ROWST;
        float cx = row[0], cy = row[1], w = row[2], h = row[3];
        float hw = __fmul_rn(w, 0.5f), hh = __fmul_rn(h, 0.5f);
        size_t bo = ((size_t)img * KSEL + r) * 4;
        g_boxes[bo + 0] = __fsub_rn(cx, hw);
        g_boxes[bo + 1] = __fsub_rn(cy, hh);
        g_boxes[bo + 2] = __fadd_rn(cx, hw);
        g_boxes[bo + 3] = __fadd_rn(cy, hh);
        g_scorea[(size_t)img * KSEL + r] = score;
        g_clsa[(size_t)img * KSEL + r] = (float)g_clstmp[(size_t)img * NBOX + n];
    }
}

// One block per image: greedy NMS with on-the-fly IoU vs kept set (in shared).
// Stops once MAXDET boxes are kept (later kept boxes never appear in output).
__global__ __launch_bounds__(256) void nms_out_kernel(float* __restrict__ out,
                                                      float* __restrict__ outvalid,
                                                      int write_valid) {
    __shared__ float4 kept[MAXDET];
    __shared__ int s_k;
    __shared__ int s_sup;
    const int img = blockIdx.x;
    const int tid = threadIdx.x;
    const float* bb = g_boxes + (size_t)img * KSEL * 4;
    const float* sc = g_scorea + (size_t)img * KSEL;
    const float* cl = g_clsa + (size_t)img * KSEL;
    if (tid == 0) s_k = 0;
    __syncthreads();

    for (int i = 0; i < KSEL; ++i) {
        float s = sc[i];
        if (!(s > 0.0f)) break;           // sorted desc: rest are invalid
        float clsv = cl[i];
        float off = __fmul_rn(clsv, MAXWH);
        float bx1 = __fadd_rn(bb[i * 4 + 0], off);
        float by1 = __fadd_rn(bb[i * 4 + 1], off);
        float bx2 = __fadd_rn(bb[i * 4 + 2], off);
        float by2 = __fadd_rn(bb[i * 4 + 3], off);
        if (tid == 0) s_sup = 0;
        __syncthreads();                  // sync1: reset visible, s_k stable
        int kc = s_k;
        float ai = __fmul_rn(__fsub_rn(bx2, bx1), __fsub_rn(by2, by1));
        for (int t = tid; t < kc; t += blockDim.x) {
            float4 kb = kept[t];
            float lx = fmaxf(bx1, kb.x);
            float ly = fmaxf(by1, kb.y);
            float rx = fminf(bx2, kb.z);
            float ry = fminf(by2, kb.w);
            float iw = fmaxf(__fsub_rn(rx, lx), 0.0f);
            float ih = fmaxf(__fsub_rn(ry, ly), 0.0f);
            float inter = __fmul_rn(iw, ih);
            float ak = __fmul_rn(__fsub_rn(kb.z, kb.x), __fsub_rn(kb.w, kb.y));
            float denom = __fadd_rn(__fsub_rn(__fadd_rn(ai, ak), inter), 1e-9f);
            if (__fdiv_rn(inter, denom) > IOU_TH) s_sup = 1;
        }
        __syncthreads();                  // sync2: all checks done
        int sup = s_sup;
        __syncthreads();                  // sync3: protect s_sup read vs next reset
        if (!sup) {
            if (tid == 0) {
                int k = s_k;
                kept[k] = make_float4(bx1, by1, bx2, by2);
                float* orow = out + ((size_t)img * MAXDET + k) * 6;
                orow[0] = bb[i * 4 + 0];
                orow[1] = bb[i * 4 + 1];
                orow[2] = bb[i * 4 + 2];
                orow[3] = bb[i * 4 + 3];
                orow[4] = s;
                orow[5] = clsv;
                if (write_valid) outvalid[(size_t)img * MAXDET + k] = 1.0f;
                s_k = k + 1;
            }
            __syncthreads();              // sync4: kept/s_k visible
            if (s_k >= MAXDET) break;
        }
    }
    __syncthreads();
    int kc = s_k;
    for (int e = tid; e < (MAXDET - kc) * 6; e += blockDim.x)
        out[(size_t)img * MAXDET * 6 + (size_t)kc * 6 + e] = 0.0f;
    if (write_valid)
        for (int r = kc + tid; r < MAXDET; r += blockDim.x)
            outvalid[(size_t)img * MAXDET + r] = 0.0f;
}

extern "C" void kernel_launch(void* const* d_in, const int* in_sizes, int n_in,
                              void* d_out, int out_size) {
    const float* x = (const float*)d_in[0];
    float* out = (float*)d_out;
    // Output layout: out (16,300,6) float32 followed by valid (16,300) as 0/1
    // in the same dtype, if the buffer is large enough to hold it.
    int write_valid = (out_size >= BIMG * MAXDET * 7) ? 1 : 0;
    float* outvalid = out + (size_t)BIMG * MAXDET * 6;
    select_sort_kernel<<<BIMG, 1024>>>(x);
    nms_out_kernel<<<BIMG, 256>>>(out, outvalid, write_valid);
}

// round 2
// speedup vs baseline: 1.1742x; 1.1742x over previous
#include <cuda_runtime.h>
#include <cstdint>

#define BIMG 16
#define NBOX 25200
#define ROWST 85
#define NCLS 80
#define KSEL 4096
#define MAXDET 300
#define CHUNK 256
#define CONF_TH 0.6f
#define IOU_TH 0.45f
#define MAXWH 7680.0f

// ---- device scratch ----
__device__ uint64_t g_selkey[BIMG * NBOX];   // (fmap(masked obj)<<32) | ~idx
__device__ uint64_t g_sortkey[BIMG * NBOX];  // (fmap(score)<<32) | fmap(masked obj)
__device__ unsigned char g_cls[BIMG * NBOX]; // argmax class
__device__ float    g_boxes[BIMG * KSEL * 4];
__device__ float    g_scorea[BIMG * KSEL];
__device__ float    g_clsa[BIMG * KSEL];

__device__ __forceinline__ uint32_t fmap(float f) {
    uint32_t u = __float_as_uint(f);
    return (u & 0x80000000u) ? ~u : (u | 0x80000000u);
}
__device__ __forceinline__ float funmap(uint32_t u) {
    u = (u & 0x80000000u) ? (u & 0x7FFFFFFFu) : ~u;
    return __uint_as_float(u);
}

// ================= K0: full-chip precompute (coalesced pass over input) ====
// One warp per row: max/argmax over 80 class scores, obj, build both keys.
__global__ __launch_bounds__(256) void precompute_kernel(const float* __restrict__ x) {
    const int wid = threadIdx.x >> 5, lane = threadIdx.x & 31;
    const int row = blockIdx.x * 8 + wid;
    if (row >= BIMG * NBOX) return;
    const int img = row / NBOX;
    const int n = row - img * NBOX;
    const float* R = x + (size_t)row * ROWST;

    float obj = R[4];                 // broadcast load
    float best = -1.0f; int bidx = NCLS;
    // j = lane, lane+32, lane+64 (ascending per lane, strict > keeps lowest idx)
    float v = R[5 + lane];
    if (v > best) { best = v; bidx = lane; }
    v = R[5 + 32 + lane];
    if (v > best) { best = v; bidx = lane + 32; }
    if (lane < 16) {
        v = R[5 + 64 + lane];
        if (v > best) { best = v; bidx = lane + 64; }
    }
    #pragma unroll
    for (int off = 16; off > 0; off >>= 1) {
        float ov = __shfl_down_sync(0xFFFFFFFFu, best, off);
        int   oi = __shfl_down_sync(0xFFFFFFFFu, bidx, off);
        if (ov > best || (ov == best && oi < bidx)) { best = ov; bidx = oi; }
    }
    if (lane == 0) {
        bool valid = obj > CONF_TH;
        float m = valid ? obj : -1.0f;
        float score = valid ? __fmul_rn(obj, best) : -1.0f;
        uint32_t mobj = fmap(m);
        g_selkey[row]  = ((uint64_t)mobj << 32) | (uint32_t)(~(uint32_t)n);
        g_sortkey[row] = ((uint64_t)fmap(score) << 32) | (uint64_t)mobj;
        g_cls[row] = (unsigned char)bidx;
    }
}

// ================= K1: per-image exact top-K select + sort =================
__global__ __launch_bounds__(1024) void select_sort_kernel(const float* __restrict__ x) {
    __shared__ uint64_t sk[KSEL];
    __shared__ uint16_t sn[KSEL];
    __shared__ uint32_t hist[256];
    __shared__ uint64_t s_prefix;
    __shared__ int s_rem;
    __shared__ int s_cnt;

    const int img = blockIdx.x;
    const int tid = threadIdx.x;
    const int bs  = blockDim.x;
    const uint64_t* keys = g_selkey + (size_t)img * NBOX;

    if (tid == 0) { s_prefix = 0ULL; s_rem = KSEL; s_cnt = 0; }
    __syncthreads();

    // 8-pass MSB radix select of exact K-th largest key (keys all distinct).
    for (int d = 7; d >= 0; --d) {
        for (int b = tid; b < 256; b += bs) hist[b] = 0;
        __syncthreads();
        const int shift = d * 8;
        const uint64_t hmask = (d == 7) ? 0ULL : ~(((uint64_t)1 << ((d + 1) * 8)) - 1ULL);
        const uint64_t pref = s_prefix;
        for (int n = tid; n < NBOX; n += bs) {
            uint64_t k = keys[n];
            if ((k & hmask) == pref) {
                uint32_t bin = (uint32_t)(k >> shift) & 0xFFu;
                unsigned am = __activemask();
                unsigned mm = __match_any_sync(am, bin);
                int leader = __ffs(mm) - 1;
                if ((int)(tid & 31) == leader) atomicAdd(&hist[bin], (uint32_t)__popc(mm));
            }
        }
        __syncthreads();
        if (tid == 0) {
            int rem = s_rem;
            int b = 255;
            for (; b > 0; --b) {
                int c = (int)hist[b];
                if (rem <= c) break;
                rem -= c;
            }
            s_prefix = pref | ((uint64_t)(uint32_t)b << shift);
            s_rem = rem;
        }
        __syncthreads();
    }
    const uint64_t T = s_prefix;

    // Gather candidate indices
    for (int n = tid; n < NBOX; n += bs) {
        if (keys[n] >= T) {
            int p = atomicAdd(&s_cnt, 1);
            sn[p] = (uint16_t)n;
        }
    }
    __syncthreads();

    // Fetch precomputed sort keys
    for (int c = tid; c < KSEL; c += bs)
        sk[c] = g_sortkey[(size_t)img * NBOX + sn[c]];
    __syncthreads();

    // Bitonic sort descending by (score, masked obj), tie -> idx asc.
    for (unsigned kk = 2; kk <= KSEL; kk <<= 1) {
        for (unsigned j = kk >> 1; j > 0; j >>= 1) {
            __syncthreads();
            for (unsigned i = tid; i < KSEL; i += bs) {
                unsigned ixj = i ^ j;
                if (ixj > i) {
                    uint64_t a = sk[i], b = sk[ixj];
                    uint16_t na = sn[i], nb = sn[ixj];
                    bool gt_i = (a > b) || (a == b && na < nb);
                    bool desc = ((i & kk) == 0);
                    if (gt_i != desc) { sk[i] = b; sk[ixj] = a; sn[i] = nb; sn[ixj] = na; }
                }
            }
        }
    }
    __syncthreads();

    // Emit sorted boxes/score/cls (reference float op order for xywh2xyxy)
    for (int r = tid; r < KSEL; r += bs) {
        int n = sn[r];
        float score = funmap((uint32_t)(sk[r] >> 32));
        const float* row = x + ((size_t)img * NBOX + n) * ROWST;
        float cx = row[0], cy = row[1], w = row[2], h = row[3];
        float hw = __fmul_rn(w, 0.5f), hh = __fmul_rn(h, 0.5f);
        size_t bo = ((size_t)img * KSEL + r) * 4;
        g_boxes[bo + 0] = __fsub_rn(cx, hw);
        g_boxes[bo + 1] = __fsub_rn(cy, hh);
        g_boxes[bo + 2] = __fadd_rn(cx, hw);
        g_boxes[bo + 3] = __fadd_rn(cy, hh);
        g_scorea[(size_t)img * KSEL + r] = score;
        g_clsa[(size_t)img * KSEL + r] = (float)g_cls[(size_t)img * NBOX + n];
    }
}

// ================= K2: chunked greedy NMS ==================================
__device__ __forceinline__ int iou_gt(float4 a, float4 b) {
    float lx = fmaxf(a.x, b.x), ly = fmaxf(a.y, b.y);
    float rx = fminf(a.z, b.z), ry = fminf(a.w, b.w);
    float iw = fmaxf(__fsub_rn(rx, lx), 0.0f);
    float ih = fmaxf(__fsub_rn(ry, ly), 0.0f);
    float inter = __fmul_rn(iw, ih);
    float aa = __fmul_rn(__fsub_rn(a.z, a.x), __fsub_rn(a.w, a.y));
    float ab = __fmul_rn(__fsub_rn(b.z, b.x), __fsub_rn(b.w, b.y));
    float denom = __fadd_rn(__fsub_rn(__fadd_rn(aa, ab), inter), 1e-9f);
    return __fdiv_rn(inter, denom) > IOU_TH;
}

__global__ __launch_bounds__(CHUNK) void nms_out_kernel(float* __restrict__ out,
                                                        float* __restrict__ outvalid,
                                                        int write_valid) {
    __shared__ float4 kept[MAXDET];
    __shared__ float4 cob[CHUNK];
    __shared__ float  cscore[CHUNK];
    __shared__ float  ccls[CHUNK];
    __shared__ int    ssup[CHUNK];
    __shared__ uint32_t pm[CHUNK][8];
    __shared__ int    klist[CHUNK];
    __shared__ int    s_k, s_cnt;

    const int img = blockIdx.x;
    const int tid = threadIdx.x;
    const float4* bb = (const float4*)(g_boxes + (size_t)img * KSEL * 4);
    const float* sc = g_scorea + (size_t)img * KSEL;
    const float* cl = g_clsa + (size_t)img * KSEL;
    if (tid == 0) { s_k = 0; }
    __syncthreads();

    for (int cb = 0; cb < KSEL / CHUNK; ++cb) {
        const int base = cb * CHUNK;
        float s = sc[base + tid];
        float clsv = cl[base + tid];
        float4 b = bb[base + tid];
        float off = __fmul_rn(clsv, MAXWH);
        float4 ob = make_float4(__fadd_rn(b.x, off), __fadd_rn(b.y, off),
                                __fadd_rn(b.z, off), __fadd_rn(b.w, off));
        cob[tid] = ob;
        cscore[tid] = s;
        ccls[tid] = clsv;
        int nv = __syncthreads_count(s > 0.0f);   // valid entries form a prefix
        if (nv == 0) break;

        // suppressed by previously-kept boxes?
        int kc = s_k;
        int sup = 0;
        for (int t = 0; t < kc; ++t)
            sup |= iou_gt(ob, kept[t]);
        ssup[tid] = sup;

        // pairwise IoU bitmask: row tid vs all chunk members
        uint32_t w = 0;
        #pragma unroll 4
        for (int j = 0; j < CHUNK; ++j) {
            w |= (uint32_t)iou_gt(ob, cob[j]) << (j & 31);
            if ((j & 31) == 31) { pm[tid][j >> 5] = w; w = 0; }
        }
        __syncthreads();

        // serial resolution (bit ops only)
        if (tid == 0) {
            uint32_t S[8] = {0, 0, 0, 0, 0, 0, 0, 0};
            int cnt = 0;
            int kcur = s_k;
            for (int i = 0; i < nv; ++i) {
                if (ssup[i]) continue;
                if ((S[i >> 5] >> (i & 31)) & 1u) continue;
                klist[cnt++] = i;
                #pragma unroll
                for (int q = 0; q < 8; ++q) S[q] |= pm[i][q];
                if (kcur + cnt >= MAXDET) break;
            }
            s_cnt = cnt;
        }
        __syncthreads();

        // append kept + write output rows
        int cnt = s_cnt;
        kc = s_k;
        if (tid < cnt) {
            int i = klist[tid];
            int kpos = kc + tid;
            kept[kpos] = cob[i];
            float4 orig = bb[base + i];
            float* orow = out + ((size_t)img * MAXDET + kpos) * 6;
            orow[0] = orig.x; orow[1] = orig.y; orow[2] = orig.z; orow[3] = orig.w;
            orow[4] = cscore[i]; orow[5] = ccls[i];
            if (write_valid) outvalid[(size_t)img * MAXDET + kpos] = 1.0f;
        }
        if (tid == 0) s_k = kc + cnt;
        __syncthreads();
        if (s_k >= MAXDET || nv < CHUNK) break;
    }
    __syncthreads();
    int kc = s_k;
    for (int e = tid; e < (MAXDET - kc) * 6; e += blockDim.x)
        out[(size_t)img * MAXDET * 6 + (size_t)kc * 6 + e] = 0.0f;
    if (write_valid)
        for (int r = kc + tid; r < MAXDET; r += blockDim.x)
            outvalid[(size_t)img * MAXDET + r] = 0.0f;
}

extern "C" void kernel_launch(void* const* d_in, const int* in_sizes, int n_in,
                              void* d_out, int out_size) {
    const float* x = (const float*)d_in[0];
    float* out = (float*)d_out;
    int write_valid = (out_size >= BIMG * MAXDET * 7) ? 1 : 0;
    float* outvalid = out + (size_t)BIMG * MAXDET * 6;
    precompute_kernel<<<(BIMG * NBOX + 7) / 8, 256>>>(x);
    select_sort_kernel<<<BIMG, 1024>>>(x);
    nms_out_kernel<<<BIMG, CHUNK>>>(out, outvalid, write_valid);
}

// round 5
// speedup vs baseline: 1.4537x; 1.2381x over previous
#include <cuda_runtime.h>
#include <cstdint>

#define BIMG 16
#define NBOX 25200
#define ROWST 85
#define NCLS 80
#define KSEL 4096
#define MAXDET 300
#define CHUNK 256
#define CONF_TH 0.6f
#define IOU_TH 0.45f
#define MAXWH 7680.0f
#define NBPI 13            // blocks per image for hist/classify (13*2048 >= 25200)
#define HBINS 4096

// ---- device scratch ----
__device__ uint32_t g_mobj[BIMG * NBOX];        // fmap(masked obj)
__device__ uint32_t g_hist[BIMG * HBINS];       // per-image 12-bit histogram
__device__ int      g_thB[BIMG];                // threshold bin
__device__ int      g_thr[BIMG];                // rank within bin
__device__ int      g_candcnt[BIMG];
__device__ int      g_bndcnt[BIMG];
__device__ uint16_t g_cand[BIMG * KSEL];        // selected row indices (unordered)
__device__ uint64_t g_bnd[BIMG * NBOX];         // boundary keys (mobj<<32)|~n
__device__ uint64_t g_skey[BIMG * KSEL];        // (fmap(score)<<32)|mobj
__device__ uint32_t g_pay[BIMG * KSEL];         // (n<<12)|ci
__device__ float4   g_boxu[BIMG * KSEL];        // unsorted xyxy
__device__ float    g_clsu[BIMG * KSEL];        // unsorted cls
__device__ float    g_boxes[BIMG * KSEL * 4];   // sorted xyxy
__device__ float    g_scorea[BIMG * KSEL];      // sorted scores
__device__ float    g_clsa[BIMG * KSEL];        // sorted cls

__device__ __forceinline__ uint32_t fmap(float f) {
    uint32_t u = __float_as_uint(f);
    return (u & 0x80000000u) ? ~u : (u | 0x80000000u);
}
__device__ __forceinline__ float funmap(uint32_t u) {
    u = (u & 0x80000000u) ? (u & 0x7FFFFFFFu) : ~u;
    return __uint_as_float(u);
}

// ---- K0: zero counters/histograms -----------------------------------------
__global__ void zero_kernel() {
    int idx = blockIdx.x * blockDim.x + threadIdx.x;
    int total = BIMG * HBINS;
    for (int i = idx; i < total; i += gridDim.x * blockDim.x) g_hist[i] = 0;
    if (idx < BIMG) { g_candcnt[idx] = 0; g_bndcnt[idx] = 0; }
}

// ---- K1: mobj + 12-bit histogram (full chip, obj column only) -------------
__global__ __launch_bounds__(256) void hist_kernel(const float* __restrict__ x) {
    __shared__ uint32_t sh[HBINS];
    const int img = blockIdx.x / NBPI;
    const int blk = blockIdx.x % NBPI;
    const int tid = threadIdx.x;
    for (int b = tid; b < HBINS; b += 256) sh[b] = 0;
    __syncthreads();
    const int base = blk * 2048;
    #pragma unroll
    for (int i = 0; i < 8; ++i) {
        int n = base + i * 256 + tid;
        if (n < NBOX) {
            float obj = __ldg(&x[((size_t)img * NBOX + n) * ROWST + 4]);
            float m = obj > CONF_TH ? obj : -1.0f;
            uint32_t mo = fmap(m);
            g_mobj[(size_t)img * NBOX + n] = mo;
            atomicAdd(&sh[mo >> 20], 1u);
        }
    }
    __syncthreads();
    for (int b = tid; b < HBINS; b += 256) {
        uint32_t c = sh[b];
        if (c) atomicAdd(&g_hist[img * HBINS + b], c);
    }
}

// ---- K2: find threshold bin B + rank r per image --------------------------
__global__ __launch_bounds__(256) void thresh_kernel() {
    __shared__ uint32_t segsum[256];
    const int img = blockIdx.x;
    const int tid = threadIdx.x;
    const uint32_t* h = g_hist + img * HBINS;
    // segment t covers bins [4095-16t .. 4080-16t] (descending order of t)
    uint32_t s = 0;
    for (int j = 0; j < 16; ++j) s += h[4095 - 16 * tid - j];
    segsum[tid] = s;
    __syncthreads();
    if (tid == 0) {
        int cum = 0, B = 0, r = KSEL;
        for (int t = 0; t < 256; ++t) {
            if (cum + (int)segsum[t] >= KSEL) {
                for (int j = 0; j < 16; ++j) {
                    int b = 4095 - 16 * t - j;
                    int c = (int)h[b];
                    if (cum + c >= KSEL) { B = b; r = KSEL - cum; break; }
                    cum += c;
                }
                break;
            }
            cum += (int)segsum[t];
        }
        g_thB[img] = B;
        g_thr[img] = r;
    }
}

// ---- K3: classify rows: definite candidates vs boundary bin ---------------
__global__ __launch_bounds__(256) void classify_kernel() {
    const int img = blockIdx.x / NBPI;
    const int blk = blockIdx.x % NBPI;
    const int tid = threadIdx.x;
    const int B = g_thB[img];
    const int base = blk * 2048;
    #pragma unroll
    for (int i = 0; i < 8; ++i) {
        int n = base + i * 256 + tid;
        if (n < NBOX) {
            uint32_t mo = g_mobj[(size_t)img * NBOX + n];
            int b = (int)(mo >> 20);
            if (b > B) {
                int pos = atomicAdd(&g_candcnt[img], 1);
                g_cand[img * KSEL + pos] = (uint16_t)n;
            } else if (b == B) {
                int pos = atomicAdd(&g_bndcnt[img], 1);
                g_bnd[(size_t)img * NBOX + pos] =
                    ((uint64_t)mo << 32) | (uint32_t)(~(uint32_t)n);
            }
        }
    }
}

// ---- K4: exact top-r among boundary keys, append to candidates ------------
__global__ __launch_bounds__(1024) void bnd_select_kernel() {
    __shared__ uint32_t hist[256];
    __shared__ uint64_t s_prefix;
    __shared__ int s_rem;
    const int img = blockIdx.x;
    const int tid = threadIdx.x;
    const int bs = blockDim.x;
    const int m = g_bndcnt[img];
    const int r = g_thr[img];
    const uint64_t* keys = g_bnd + (size_t)img * NBOX;
    uint64_t T = 0;
    if (r < m) {
        if (tid == 0) { s_prefix = 0ULL; s_rem = r; }
        __syncthreads();
        for (int d = 7; d >= 0; --d) {
            for (int b = tid; b < 256; b += bs) hist[b] = 0;
            __syncthreads();
            const int shift = d * 8;
            const uint64_t hmask = (d == 7) ? 0ULL : ~(((uint64_t)1 << ((d + 1) * 8)) - 1ULL);
            const uint64_t pref = s_prefix;
            for (int j = tid; j < m; j += bs) {
                uint64_t k = keys[j];
                if ((k & hmask) == pref) {
                    uint32_t bin = (uint32_t)(k >> shift) & 0xFFu;
                    unsigned am = __activemask();
                    unsigned mm = __match_any_sync(am, bin);
                    int leader = __ffs(mm) - 1;
                    if ((int)(tid & 31) == leader) atomicAdd(&hist[bin], (uint32_t)__popc(mm));
                }
            }
            __syncthreads();
            if (tid == 0) {
                int rem = s_rem;
                int b = 255;
                for (; b > 0; --b) {
                    int c = (int)hist[b];
                    if (rem <= c) break;
                    rem -= c;
                }
                s_prefix = pref | ((uint64_t)(uint32_t)b << shift);
                s_rem = rem;
            }
            __syncthreads();
        }
        T = s_prefix;
    }
    __syncthreads();
    for (int j = tid; j < m; j += bs) {
        uint64_t k = keys[j];
        if (k >= T) {
            int pos = atomicAdd(&g_candcnt[img], 1);
            g_cand[img * KSEL + pos] = (uint16_t)(~(uint32_t)k);
        }
    }
}

// ---- K5: full-chip score/argmax/box for the 65536 selected rows -----------
__global__ __launch_bounds__(256) void score_kernel(const float* __restrict__ x) {
    const int wid = threadIdx.x >> 5, lane = threadIdx.x & 31;
    const int cidx = blockIdx.x * 8 + wid;
    if (cidx >= BIMG * KSEL) return;
    const int img = cidx >> 12;          // / KSEL
    const int ci = cidx & (KSEL - 1);
    const int n = g_cand[cidx];
    const float* R = x + ((size_t)img * NBOX + n) * ROWST;

    float obj = __ldg(&R[4]);
    float best = -1.0f; int bidx = NCLS;
    float v = __ldg(&R[5 + lane]);
    if (v > best) { best = v; bidx = lane; }
    v = __ldg(&R[5 + 32 + lane]);
    if (v > best) { best = v; bidx = lane + 32; }
    if (lane < 16) {
        v = __ldg(&R[5 + 64 + lane]);
        if (v > best) { best = v; bidx = lane + 64; }
    }
    #pragma unroll
    for (int off = 16; off > 0; off >>= 1) {
        float ov = __shfl_down_sync(0xFFFFFFFFu, best, off);
        int   oi = __shfl_down_sync(0xFFFFFFFFu, bidx, off);
        if (ov > best || (ov == best && oi < bidx)) { best = ov; bidx = oi; }
    }
    if (lane == 0) {
        bool valid = obj > CONF_TH;
        float score = valid ? __fmul_rn(obj, best) : -1.0f;
        uint32_t mo = g_mobj[(size_t)img * NBOX + n];
        g_skey[cidx] = ((uint64_t)fmap(score) << 32) | (uint64_t)mo;
        g_pay[cidx] = ((uint32_t)n << 12) | (uint32_t)ci;
        float cx = __ldg(&R[0]), cy = __ldg(&R[1]), w = __ldg(&R[2]), h = __ldg(&R[3]);
        float hw = __fmul_rn(w, 0.5f), hh = __fmul_rn(h, 0.5f);
        g_boxu[cidx] = make_float4(__fsub_rn(cx, hw), __fsub_rn(cy, hh),
                                   __fadd_rn(cx, hw), __fadd_rn(cy, hh));
        g_clsu[cidx] = (float)bidx;
    }
}

// ---- K6: per-image bitonic sort + emit sorted arrays ----------------------
__global__ __launch_bounds__(1024) void sort_kernel() {
    __shared__ uint64_t sk[KSEL];   // 32 KB
    __shared__ uint32_t sp[KSEL];   // 16 KB
    const int img = blockIdx.x;
    const int tid = threadIdx.x;
    const int bs = blockDim.x;
    for (int i = tid; i < KSEL; i += bs) {
        sk[i] = g_skey[img * KSEL + i];
        sp[i] = g_pay[img * KSEL + i];
    }
    for (unsigned kk = 2; kk <= KSEL; kk <<= 1) {
        for (unsigned j = kk >> 1; j > 0; j >>= 1) {
            __syncthreads();
            for (unsigned i = tid; i < KSEL; i += bs) {
                unsigned ixj = i ^ j;
                if (ixj > i) {
                    uint64_t a = sk[i], b = sk[ixj];
                    uint32_t pa = sp[i], pb = sp[ixj];
                    bool gt_i = (a > b) || (a == b && (pa >> 12) < (pb >> 12));
                    bool desc = ((i & kk) == 0);
                    if (gt_i != desc) { sk[i] = b; sk[ixj] = a; sp[i] = pb; sp[ixj] = pa; }
                }
            }
        }
    }
    __syncthreads();
    for (int r = tid; r < KSEL; r += bs) {
        uint32_t c = sp[r] & (KSEL - 1);
        float4 bx = g_boxu[img * KSEL + c];
        size_t bo = ((size_t)img * KSEL + r) * 4;
        g_boxes[bo + 0] = bx.x; g_boxes[bo + 1] = bx.y;
        g_boxes[bo + 2] = bx.z; g_boxes[bo + 3] = bx.w;
        g_scorea[img * KSEL + r] = funmap((uint32_t)(sk[r] >> 32));
        g_clsa[img * KSEL + r] = g_clsu[img * KSEL + c];
    }
}

// ---- K7: chunked greedy NMS (unchanged, proven exact) ---------------------
__device__ __forceinline__ int iou_gt(float4 a, float4 b) {
    float lx = fmaxf(a.x, b.x), ly = fmaxf(a.y, b.y);
    float rx = fminf(a.z, b.z), ry = fminf(a.w, b.w);
    float iw = fmaxf(__fsub_rn(rx, lx), 0.0f);
    float ih = fmaxf(__fsub_rn(ry, ly), 0.0f);
    float inter = __fmul_rn(iw, ih);
    float aa = __fmul_rn(__fsub_rn(a.z, a.x), __fsub_rn(a.w, a.y));
    float ab = __fmul_rn(__fsub_rn(b.z, b.x), __fsub_rn(b.w, b.y));
    float denom = __fadd_rn(__fsub_rn(__fadd_rn(aa, ab), inter), 1e-9f);
    return __fdiv_rn(inter, denom) > IOU_TH;
}

__global__ __launch_bounds__(CHUNK) void nms_out_kernel(float* __restrict__ out,
                                                        float* __restrict__ outvalid,
                                                        int write_valid) {
    __shared__ float4 kept[MAXDET];
    __shared__ float4 cob[CHUNK];
    __shared__ float  cscore[CHUNK];
    __shared__ float  ccls[CHUNK];
    __shared__ int    ssup[CHUNK];
    __shared__ uint32_t pm[CHUNK][8];
    __shared__ int    klist[CHUNK];
    __shared__ int    s_k, s_cnt;

    const int img = blockIdx.x;
    const int tid = threadIdx.x;
    const float4* bb = (const float4*)(g_boxes + (size_t)img * KSEL * 4);
    const float* sc = g_scorea + (size_t)img * KSEL;
    const float* cl = g_clsa + (size_t)img * KSEL;
    if (tid == 0) { s_k = 0; }
    __syncthreads();

    for (int cb = 0; cb < KSEL / CHUNK; ++cb) {
        const int base = cb * CHUNK;
        float s = sc[base + tid];
        float clsv = cl[base + tid];
        float4 b = bb[base + tid];
        float off = __fmul_rn(clsv, MAXWH);
        float4 ob = make_float4(__fadd_rn(b.x, off), __fadd_rn(b.y, off),
                                __fadd_rn(b.z, off), __fadd_rn(b.w, off));
        cob[tid] = ob;
        cscore[tid] = s;
        ccls[tid] = clsv;
        int nv = __syncthreads_count(s > 0.0f);
        if (nv == 0) break;

        int kc = s_k;
        int sup = 0;
        for (int t = 0; t < kc; ++t)
            sup |= iou_gt(ob, kept[t]);
        ssup[tid] = sup;

        uint32_t w = 0;
        #pragma unroll 4
        for (int j = 0; j < CHUNK; ++j) {
            w |= (uint32_t)iou_gt(ob, cob[j]) << (j & 31);
            if ((j & 31) == 31) { pm[tid][j >> 5] = w; w = 0; }
        }
        __syncthreads();

        if (tid == 0) {
            uint32_t S[8] = {0, 0, 0, 0, 0, 0, 0, 0};
            int cnt = 0;
            int kcur = s_k;
            for (int i = 0; i < nv; ++i) {
                if (ssup[i]) continue;
                if ((S[i >> 5] >> (i & 31)) & 1u) continue;
                klist[cnt++] = i;
                #pragma unroll
                for (int q = 0; q < 8; ++q) S[q] |= pm[i][q];
                if (kcur + cnt >= MAXDET) break;
            }
            s_cnt = cnt;
        }
        __syncthreads();

        int cnt = s_cnt;
        kc = s_k;
        if (tid < cnt) {
            int i = klist[tid];
            int kpos = kc + tid;
            kept[kpos] = cob[i];
            float4 orig = bb[base + i];
            float* orow = out + ((size_t)img * MAXDET + kpos) * 6;
            orow[0] = orig.x; orow[1] = orig.y; orow[2] = orig.z; orow[3] = orig.w;
            orow[4] = cscore[i]; orow[5] = ccls[i];
            if (write_valid) outvalid[(size_t)img * MAXDET + kpos] = 1.0f;
        }
        if (tid == 0) s_k = kc + cnt;
        __syncthreads();
        if (s_k >= MAXDET || nv < CHUNK) break;
    }
    __syncthreads();
    int kc = s_k;
    for (int e = tid; e < (MAXDET - kc) * 6; e += blockDim.x)
        out[(size_t)img * MAXDET * 6 + (size_t)kc * 6 + e] = 0.0f;
    if (write_valid)
        for (int r = kc + tid; r < MAXDET; r += blockDim.x)
            outvalid[(size_t)img * MAXDET + r] = 0.0f;
}

extern "C" void kernel_launch(void* const* d_in, const int* in_sizes, int n_in,
                              void* d_out, int out_size) {
    const float* x = (const float*)d_in[0];
    float* out = (float*)d_out;
    int write_valid = (out_size >= BIMG * MAXDET * 7) ? 1 : 0;
    float* outvalid = out + (size_t)BIMG * MAXDET * 6;
    zero_kernel<<<128, 512>>>();
    hist_kernel<<<BIMG * NBPI, 256>>>(x);
    thresh_kernel<<<BIMG, 256>>>();
    classify_kernel<<<BIMG * NBPI, 256>>>();
    bnd_select_kernel<<<BIMG, 1024>>>();
    score_kernel<<<(BIMG * KSEL + 7) / 8, 256>>>(x);
    sort_kernel<<<BIMG, 1024>>>();
    nms_out_kernel<<<BIMG, CHUNK>>>(out, outvalid, write_valid);
}

// round 6
// speedup vs baseline: 1.4939x; 1.0276x over previous
#include <cuda_runtime.h>
#include <cstdint>

#define BIMG 16
#define NBOX 25200
#define ROWST 85
#define NCLS 80
#define KSEL 4096
#define MAXDET 300
#define CHUNK 256
#define CONF_TH 0.6f
#define IOU_TH 0.45f
#define MAXWH 7680.0f
#define NBPI 13            // blocks per image for hist/classify (13*2048 >= 25200)
#define HBINS 4096

// ---- device scratch (zero-initialized at load; pipeline is self-cleaning:
// every launch leaves g_hist/g_candcnt/g_bndcnt zeroed for the next replay) ----
__device__ uint32_t g_mobj[BIMG * NBOX];        // fmap(masked obj)
__device__ uint32_t g_hist[BIMG * HBINS];       // per-image 12-bit histogram
__device__ int      g_candcnt[BIMG];
__device__ int      g_bndcnt[BIMG];
__device__ uint16_t g_cand[BIMG * KSEL];        // selected row indices (unordered)
__device__ uint64_t g_bnd[BIMG * NBOX];         // boundary keys (mobj<<32)|~n
__device__ uint64_t g_skey[BIMG * KSEL];        // (fmap(score)<<32)|mobj
__device__ uint32_t g_pay[BIMG * KSEL];         // (n<<12)|ci
__device__ float4   g_boxu[BIMG * KSEL];        // unsorted xyxy
__device__ float    g_clsu[BIMG * KSEL];        // unsorted cls
__device__ float    g_boxes[BIMG * KSEL * 4];   // sorted xyxy
__device__ float    g_scorea[BIMG * KSEL];      // sorted scores
__device__ float    g_clsa[BIMG * KSEL];        // sorted cls

__device__ __forceinline__ uint32_t fmap(float f) {
    uint32_t u = __float_as_uint(f);
    return (u & 0x80000000u) ? ~u : (u | 0x80000000u);
}
__device__ __forceinline__ float funmap(uint32_t u) {
    u = (u & 0x80000000u) ? (u & 0x7FFFFFFFu) : ~u;
    return __uint_as_float(u);
}

// Threshold (bin B, within-bin rank r) from a per-image histogram. 256 threads.
__device__ __forceinline__ void find_threshold(const uint32_t* __restrict__ h,
                                               int tid, uint32_t* segsum,
                                               int* sB, int* sR) {
    uint32_t s = 0;
    #pragma unroll
    for (int j = 0; j < 16; ++j) s += h[4095 - 16 * tid - j];
    segsum[tid] = s;
    __syncthreads();
    if (tid == 0) {
        int cum = 0, B = 0, r = KSEL;
        for (int t = 0; t < 256; ++t) {
            if (cum + (int)segsum[t] >= KSEL) {
                for (int j = 0; j < 16; ++j) {
                    int b = 4095 - 16 * t - j;
                    int c = (int)h[b];
                    if (cum + c >= KSEL) { B = b; r = KSEL - cum; break; }
                    cum += c;
                }
                break;
            }
            cum += (int)segsum[t];
        }
        *sB = B;
        *sR = r;
    }
    __syncthreads();
}

// ---- K1: mobj + 12-bit histogram (staged loads for MLP) -------------------
__global__ __launch_bounds__(256) void hist_kernel(const float* __restrict__ x) {
    __shared__ uint32_t sh[HBINS];
    const int img = blockIdx.x / NBPI;
    const int blk = blockIdx.x % NBPI;
    const int tid = threadIdx.x;
    for (int b = tid; b < HBINS; b += 256) sh[b] = 0;
    __syncthreads();
    const int base = blk * 2048;
    float objv[8];
    int   nn[8];
    #pragma unroll
    for (int i = 0; i < 8; ++i) {
        nn[i] = base + i * 256 + tid;
        objv[i] = (nn[i] < NBOX) ? __ldg(&x[((size_t)img * NBOX + nn[i]) * ROWST + 4]) : 0.0f;
    }
    #pragma unroll
    for (int i = 0; i < 8; ++i) {
        if (nn[i] < NBOX) {
            float m = objv[i] > CONF_TH ? objv[i] : -1.0f;
            uint32_t mo = fmap(m);
            g_mobj[(size_t)img * NBOX + nn[i]] = mo;
            atomicAdd(&sh[mo >> 20], 1u);
        }
    }
    __syncthreads();
    for (int b = tid; b < HBINS; b += 256) {
        uint32_t c = sh[b];
        if (c) atomicAdd(&g_hist[img * HBINS + b], c);
    }
}

// ---- K2: threshold + classify (block-staged compaction) -------------------
__global__ __launch_bounds__(256) void classify_kernel() {
    __shared__ uint32_t segsum[256];
    __shared__ int sB, sR;
    __shared__ uint16_t scand[2048];
    __shared__ uint64_t sbnd[2048];
    __shared__ int s_nc, s_nb, s_cb, s_bb;
    const int img = blockIdx.x / NBPI;
    const int blk = blockIdx.x % NBPI;
    const int tid = threadIdx.x;
    if (tid == 0) { s_nc = 0; s_nb = 0; }
    find_threshold(g_hist + img * HBINS, tid, segsum, &sB, &sR);
    const int B = sB;

    const int base = blk * 2048;
    uint32_t mo[8];
    int nn[8];
    #pragma unroll
    for (int i = 0; i < 8; ++i) {
        nn[i] = base + i * 256 + tid;
        mo[i] = (nn[i] < NBOX) ? g_mobj[(size_t)img * NBOX + nn[i]] : 0u;
    }
    #pragma unroll
    for (int i = 0; i < 8; ++i) {
        if (nn[i] < NBOX) {
            int b = (int)(mo[i] >> 20);
            if (b > B) {
                int p = atomicAdd(&s_nc, 1);
                scand[p] = (uint16_t)nn[i];
            } else if (b == B) {
                int p = atomicAdd(&s_nb, 1);
                sbnd[p] = ((uint64_t)mo[i] << 32) | (uint32_t)(~(uint32_t)nn[i]);
            }
        }
    }
    __syncthreads();
    if (tid == 0) {
        s_cb = atomicAdd(&g_candcnt[img], s_nc);
        s_bb = atomicAdd(&g_bndcnt[img], s_nb);
    }
    __syncthreads();
    const int nc = s_nc, nb = s_nb, cb = s_cb, bb = s_bb;
    for (int i = tid; i < nc; i += 256) g_cand[img * KSEL + cb + i] = scand[i];
    for (int i = tid; i < nb; i += 256) g_bnd[(size_t)img * NBOX + bb + i] = sbnd[i];
}

// ---- K3: exact top-r among boundary keys + self-clean ---------------------
__global__ __launch_bounds__(256) void bnd_select_kernel() {
    __shared__ uint32_t segsum[256];
    __shared__ int sB, sR;
    __shared__ uint32_t hist[256];
    __shared__ uint64_t s_prefix;
    __shared__ int s_rem;
    const int img = blockIdx.x;
    const int tid = threadIdx.x;
    const int bs = 256;
    find_threshold(g_hist + img * HBINS, tid, segsum, &sB, &sR);
    const int m = g_bndcnt[img];
    const int r = sR;
    const uint64_t* keys = g_bnd + (size_t)img * NBOX;
    uint64_t T = 0;
    if (r < m) {
        if (tid == 0) { s_prefix = 0ULL; s_rem = r; }
        __syncthreads();
        for (int d = 7; d >= 0; --d) {
            hist[tid] = 0;
            __syncthreads();
            const int shift = d * 8;
            const uint64_t hmask = (d == 7) ? 0ULL : ~(((uint64_t)1 << ((d + 1) * 8)) - 1ULL);
            const uint64_t pref = s_prefix;
            for (int j = tid; j < m; j += bs) {
                uint64_t k = keys[j];
                if ((k & hmask) == pref) {
                    uint32_t bin = (uint32_t)(k >> shift) & 0xFFu;
                    unsigned am = __activemask();
                    unsigned mm = __match_any_sync(am, bin);
                    int leader = __ffs(mm) - 1;
                    if ((int)(tid & 31) == leader) atomicAdd(&hist[bin], (uint32_t)__popc(mm));
                }
            }
            __syncthreads();
            if (tid == 0) {
                int rem = s_rem;
                int b = 255;
                for (; b > 0; --b) {
                    int c = (int)hist[b];
                    if (rem <= c) break;
                    rem -= c;
                }
                s_prefix = pref | ((uint64_t)(uint32_t)b << shift);
                s_rem = rem;
            }
            __syncthreads();
        }
        T = s_prefix;
    }
    __syncthreads();
    for (int j = tid; j < m; j += bs) {
        uint64_t k = keys[j];
        if (k >= T) {
            int pos = atomicAdd(&g_candcnt[img], 1);
            g_cand[img * KSEL + pos] = (uint16_t)(~(uint32_t)k);
        }
    }
    __syncthreads();
    // self-clean for next graph replay
    for (int i = tid; i < HBINS; i += bs) g_hist[img * HBINS + i] = 0;
    if (tid == 0) { g_candcnt[img] = 0; g_bndcnt[img] = 0; }
}

// ---- K4: full-chip score/argmax/box for the 65536 selected rows -----------
__global__ __launch_bounds__(256) void score_kernel(const float* __restrict__ x) {
    const int wid = threadIdx.x >> 5, lane = threadIdx.x & 31;
    const int cidx = blockIdx.x * 8 + wid;
    if (cidx >= BIMG * KSEL) return;
    const int img = cidx >> 12;
    const int ci = cidx & (KSEL - 1);
    const int n = g_cand[cidx];
    const float* R = x + ((size_t)img * NBOX + n) * ROWST;

    float obj = __ldg(&R[4]);
    float v0 = __ldg(&R[5 + lane]);
    float v1 = __ldg(&R[5 + 32 + lane]);
    float v2 = (lane < 16) ? __ldg(&R[5 + 64 + lane]) : -1.0f;
    float best = -1.0f; int bidx = NCLS;
    if (v0 > best) { best = v0; bidx = lane; }
    if (v1 > best) { best = v1; bidx = lane + 32; }
    if (v2 > best) { best = v2; bidx = lane + 64; }
    #pragma unroll
    for (int off = 16; off > 0; off >>= 1) {
        float ov = __shfl_down_sync(0xFFFFFFFFu, best, off);
        int   oi = __shfl_down_sync(0xFFFFFFFFu, bidx, off);
        if (ov > best || (ov == best && oi < bidx)) { best = ov; bidx = oi; }
    }
    if (lane == 0) {
        bool valid = obj > CONF_TH;
        float score = valid ? __fmul_rn(obj, best) : -1.0f;
        uint32_t mo = g_mobj[(size_t)img * NBOX + n];
        g_skey[cidx] = ((uint64_t)fmap(score) << 32) | (uint64_t)mo;
        g_pay[cidx] = ((uint32_t)n << 12) | (uint32_t)ci;
        float cx = __ldg(&R[0]), cy = __ldg(&R[1]), w = __ldg(&R[2]), h = __ldg(&R[3]);
        float hw = __fmul_rn(w, 0.5f), hh = __fmul_rn(h, 0.5f);
        g_boxu[cidx] = make_float4(__fsub_rn(cx, hw), __fsub_rn(cy, hh),
                                   __fadd_rn(cx, hw), __fadd_rn(cy, hh));
        g_clsu[cidx] = (float)bidx;
    }
}

// ---- K5: per-image bitonic sort (warp-local phases use syncwarp) ----------
__global__ __launch_bounds__(1024) void sort_kernel() {
    __shared__ uint64_t sk[KSEL];   // 32 KB
    __shared__ uint32_t sp[KSEL];   // 16 KB
    const int img = blockIdx.x;
    const int tid = threadIdx.x;
    const int bs = blockDim.x;
    for (int i = tid; i < KSEL; i += bs) {
        sk[i] = g_skey[img * KSEL + i];
        sp[i] = g_pay[img * KSEL + i];
    }
    __syncthreads();
    for (unsigned kk = 2; kk <= KSEL; kk <<= 1) {
        for (unsigned j = kk >> 1; j > 0; j >>= 1) {
            // phase j moves data within aligned 2j blocks; lanes own consecutive
            // 32-element runs, so for j < 16 (and previous phase 2j < 32) all
            // traffic is warp-local -> syncwarp suffices.
            if (j >= 16) __syncthreads(); else __syncwarp();
            for (unsigned i = tid; i < KSEL; i += bs) {
                unsigned ixj = i ^ j;
                if (ixj > i) {
                    uint64_t a = sk[i], b = sk[ixj];
                    uint32_t pa = sp[i], pb = sp[ixj];
                    bool gt_i = (a > b) || (a == b && (pa >> 12) < (pb >> 12));
                    bool desc = ((i & kk) == 0);
                    if (gt_i != desc) { sk[i] = b; sk[ixj] = a; sp[i] = pb; sp[ixj] = pa; }
                }
            }
        }
    }
    __syncthreads();
    for (int r = tid; r < KSEL; r += bs) {
        uint32_t c = sp[r] & (KSEL - 1);
        float4 bx = g_boxu[img * KSEL + c];
        size_t bo = ((size_t)img * KSEL + r) * 4;
        g_boxes[bo + 0] = bx.x; g_boxes[bo + 1] = bx.y;
        g_boxes[bo + 2] = bx.z; g_boxes[bo + 3] = bx.w;
        g_scorea[img * KSEL + r] = funmap((uint32_t)(sk[r] >> 32));
        g_clsa[img * KSEL + r] = g_clsu[img * KSEL + c];
    }
}

// ---- K6: chunked greedy NMS (unchanged, proven exact) ---------------------
__device__ __forceinline__ int iou_gt(float4 a, float4 b) {
    float lx = fmaxf(a.x, b.x), ly = fmaxf(a.y, b.y);
    float rx = fminf(a.z, b.z), ry = fminf(a.w, b.w);
    float iw = fmaxf(__fsub_rn(rx, lx), 0.0f);
    float ih = fmaxf(__fsub_rn(ry, ly), 0.0f);
    float inter = __fmul_rn(iw, ih);
    float aa = __fmul_rn(__fsub_rn(a.z, a.x), __fsub_rn(a.w, a.y));
    float ab = __fmul_rn(__fsub_rn(b.z, b.x), __fsub_rn(b.w, b.y));
    float denom = __fadd_rn(__fsub_rn(__fadd_rn(aa, ab), inter), 1e-9f);
    return __fdiv_rn(inter, denom) > IOU_TH;
}

__global__ __launch_bounds__(CHUNK) void nms_out_kernel(float* __restrict__ out,
                                                        float* __restrict__ outvalid,
                                                        int write_valid) {
    __shared__ float4 kept[MAXDET];
    __shared__ float4 cob[CHUNK];
    __shared__ float  cscore[CHUNK];
    __shared__ float  ccls[CHUNK];
    __shared__ int    ssup[CHUNK];
    __shared__ uint32_t pm[CHUNK][8];
    __shared__ int    klist[CHUNK];
    __shared__ int    s_k, s_cnt;

    const int img = blockIdx.x;
    const int tid = threadIdx.x;
    const float4* bb = (const float4*)(g_boxes + (size_t)img * KSEL * 4);
    const float* sc = g_scorea + (size_t)img * KSEL;
    const float* cl = g_clsa + (size_t)img * KSEL;
    if (tid == 0) { s_k = 0; }
    __syncthreads();

    for (int cb = 0; cb < KSEL / CHUNK; ++cb) {
        const int base = cb * CHUNK;
        float s = sc[base + tid];
        float clsv = cl[base + tid];
        float4 b = bb[base + tid];
        float off = __fmul_rn(clsv, MAXWH);
        float4 ob = make_float4(__fadd_rn(b.x, off), __fadd_rn(b.y, off),
                                __fadd_rn(b.z, off), __fadd_rn(b.w, off));
        cob[tid] = ob;
        cscore[tid] = s;
        ccls[tid] = clsv;
        int nv = __syncthreads_count(s > 0.0f);
        if (nv == 0) break;

        int kc = s_k;
        int sup = 0;
        for (int t = 0; t < kc; ++t)
            sup |= iou_gt(ob, kept[t]);
        ssup[tid] = sup;

        uint32_t w = 0;
        #pragma unroll 4
        for (int j = 0; j < CHUNK; ++j) {
            w |= (uint32_t)iou_gt(ob, cob[j]) << (j & 31);
            if ((j & 31) == 31) { pm[tid][j >> 5] = w; w = 0; }
        }
        __syncthreads();

        if (tid == 0) {
            uint32_t S[8] = {0, 0, 0, 0, 0, 0, 0, 0};
            int cnt = 0;
            int kcur = s_k;
            for (int i = 0; i < nv; ++i) {
                if (ssup[i]) continue;
                if ((S[i >> 5] >> (i & 31)) & 1u) continue;
                klist[cnt++] = i;
                #pragma unroll
                for (int q = 0; q < 8; ++q) S[q] |= pm[i][q];
                if (kcur + cnt >= MAXDET) break;
            }
            s_cnt = cnt;
        }
        __syncthreads();

        int cnt = s_cnt;
        kc = s_k;
        if (tid < cnt) {
            int i = klist[tid];
            int kpos = kc + tid;
            kept[kpos] = cob[i];
            float4 orig = bb[base + i];
            float* orow = out + ((size_t)img * MAXDET + kpos) * 6;
            orow[0] = orig.x; orow[1] = orig.y; orow[2] = orig.z; orow[3] = orig.w;
            orow[4] = cscore[i]; orow[5] = ccls[i];
            if (write_valid) outvalid[(size_t)img * MAXDET + kpos] = 1.0f;
        }
        if (tid == 0) s_k = kc + cnt;
        __syncthreads();
        if (s_k >= MAXDET || nv < CHUNK) break;
    }
    __syncthreads();
    int kc = s_k;
    for (int e = tid; e < (MAXDET - kc) * 6; e += blockDim.x)
        out[(size_t)img * MAXDET * 6 + (size_t)kc * 6 + e] = 0.0f;
    if (write_valid)
        for (int r = kc + tid; r < MAXDET; r += blockDim.x)
            outvalid[(size_t)img * MAXDET + r] = 0.0f;
}

extern "C" void kernel_launch(void* const* d_in, const int* in_sizes, int n_in,
                              void* d_out, int out_size) {
    const float* x = (const float*)d_in[0];
    float* out = (float*)d_out;
    int write_valid = (out_size >= BIMG * MAXDET * 7) ? 1 : 0;
    float* outvalid = out + (size_t)BIMG * MAXDET * 6;
    hist_kernel<<<BIMG * NBPI, 256>>>(x);
    classify_kernel<<<BIMG * NBPI, 256>>>();
    bnd_select_kernel<<<BIMG, 256>>>();
    score_kernel<<<(BIMG * KSEL + 7) / 8, 256>>>(x);
    sort_kernel<<<BIMG, 1024>>>();
    nms_out_kernel<<<BIMG, CHUNK>>>(out, outvalid, write_valid);
}